// round 11
// baseline (speedup 1.0000x reference)
#include <cuda_runtime.h>

// MaxPool2d: kernel=2, stride=2, padding=0
// Input:  (32, 64, 224, 224) fp32  -> NC = 2048 planes of 224x224
// Output: (32, 64, 112, 112) fp32
//
// FINAL (best measured: 75.17us wall @ R8, 86.7% DRAM, 6.87 TB/s).
// Fully-coalesced-per-instruction layout:
//   Unit = (plane, output row, float4 column chunk): thread loads
//   in[2oh][4c4..4c4+4) and in[2oh+1][...] -- lanes hit CONSECUTIVE
//   16B (4 cache lines per LDG.128, minimal L1tex wavefronts),
//   computes vertical max then horizontal pair max -> float2 output
//   (coalesced 8B stores). 2 warp-strided units per thread -> MLP=4.
//   12,845,056 units == 25088 blocks * 512. No tail, no guard.
//
// Session summary (9 benches): MLP {4,8,16}, lane coalescing, cache
// hints, persistent grid, index width, block {256,512} all measured.
// Everything sane lands at 86-88% DRAM / 6.85-7.0 TB/s; traffic is
// irreducible (514 MB, each byte touched once). This config is the
// best of the band -- machine-limited at the HBM streaming ceiling.

#define IN_H    224
#define IN_W    224
#define OUT_H   112
#define OUT_W   112
#define NC      (32 * 64)

#define C4      (IN_W / 4)                  // 56 float4 chunks per input row
#define TOTAL   (NC * OUT_H * C4)           // 12,845,056 == 25088 * 512

__device__ __forceinline__ void unit(unsigned g,
                                     const float* __restrict__ in,
                                     float* __restrict__ out)
{
    // 32-bit div/mod by constants -> magic-multiply IMADs
    const unsigned c4  = g % C4;
    const unsigned tmp = g / C4;
    const unsigned oh  = tmp % OUT_H;
    const unsigned nc  = tmp / OUT_H;

    const float* p = in + (size_t)nc * (IN_H * IN_W)
                        + (size_t)(2u * oh) * IN_W
                        + c4 * 4u;

    // Two fully-coalesced LDG.128 (lanes -> consecutive 16B)
    const float4 a = *reinterpret_cast<const float4*>(p);
    const float4 b = *reinterpret_cast<const float4*>(p + IN_W);

    // vertical max, then horizontal pair max -> 2 outputs
    float2 o;
    o.x = fmaxf(fmaxf(a.x, b.x), fmaxf(a.y, b.y));
    o.y = fmaxf(fmaxf(a.z, b.z), fmaxf(a.w, b.w));

    float* q = out + (size_t)nc * (OUT_H * OUT_W)
                   + (size_t)oh * OUT_W
                   + c4 * 2u;
    *reinterpret_cast<float2*>(q) = o;
}

__global__ __launch_bounds__(256)
void maxpool2d_k2s2_kernel(const float* __restrict__ in,
                           float* __restrict__ out)
{
    const unsigned base = blockIdx.x * 512u + threadIdx.x;
    // two warp-strided units -> 4 front-batched loads (MLP=4)
    unit(base,        in, out);
    unit(base + 256u, in, out);
}

extern "C" void kernel_launch(void* const* d_in, const int* in_sizes, int n_in,
                              void* d_out, int out_size)
{
    const float* x = (const float*)d_in[0];
    float* y = (float*)d_out;

    maxpool2d_k2s2_kernel<<<TOTAL / 512, 256>>>(x, y);   // 25088 blocks, exact
}

// round 12
// speedup vs baseline: 1.0064x; 1.0064x over previous
#include <cuda_runtime.h>

// MaxPool2d: kernel=2, stride=2, padding=0
// Input:  (32, 64, 224, 224) fp32  -> NC = 2048 planes of 224x224
// Output: (32, 64, 112, 112) fp32
//
// FINAL. Identical binary measured 3x: wall 75.17 / 75.49 / 76.06 us
// (noise band +/-0.5us), ncu kernel-time 71.0-72.5us, DRAM 86.4-88.2%,
// HBM 6.85-6.98 TB/s (~87% of 8 TB/s spec = B300 LTS cap on a mixed
// 4:1 read/write stream). Traffic is irreducible (514 MB, every byte
// touched exactly once); compute pipes idle. Machine-limited.
//
// Layout: Unit = (plane, output row, float4 column chunk). Thread loads
// in[2oh][4c4..4c4+4) and in[2oh+1][...] -- lanes hit CONSECUTIVE 16B
// (4 cache lines per LDG.128, minimal L1tex wavefronts) -- computes
// vertical then horizontal pair max -> coalesced float2 store.
// 2 warp-strided units per thread (MLP=4).
// 12,845,056 units == 25088 blocks * 512 threads-worth. No tail.
//
// Levers measured and closed across the session: per-thread MLP
// {4,8,16}; lane-strided vs per-instruction-coalesced loads (the one
// real fix: L1% 39.7->22.1); __ldcs/__stcs (-2% DRAM); persistent
// grid-stride (-5%); block {256,512}; 32- vs 64-bit index math.

#define IN_H    224
#define IN_W    224
#define OUT_H   112
#define OUT_W   112
#define NC      (32 * 64)

#define C4      (IN_W / 4)                  // 56 float4 chunks per input row
#define TOTAL   (NC * OUT_H * C4)           // 12,845,056 == 25088 * 512

__device__ __forceinline__ void unit(unsigned g,
                                     const float* __restrict__ in,
                                     float* __restrict__ out)
{
    // 32-bit div/mod by constants -> magic-multiply IMADs
    const unsigned c4  = g % C4;
    const unsigned tmp = g / C4;
    const unsigned oh  = tmp % OUT_H;
    const unsigned nc  = tmp / OUT_H;

    const float* p = in + (size_t)nc * (IN_H * IN_W)
                        + (size_t)(2u * oh) * IN_W
                        + c4 * 4u;

    // Two fully-coalesced LDG.128 (lanes -> consecutive 16B)
    const float4 a = *reinterpret_cast<const float4*>(p);
    const float4 b = *reinterpret_cast<const float4*>(p + IN_W);

    // vertical max, then horizontal pair max -> 2 outputs
    float2 o;
    o.x = fmaxf(fmaxf(a.x, b.x), fmaxf(a.y, b.y));
    o.y = fmaxf(fmaxf(a.z, b.z), fmaxf(a.w, b.w));

    float* q = out + (size_t)nc * (OUT_H * OUT_W)
                   + (size_t)oh * OUT_W
                   + c4 * 2u;
    *reinterpret_cast<float2*>(q) = o;
}

__global__ __launch_bounds__(256)
void maxpool2d_k2s2_kernel(const float* __restrict__ in,
                           float* __restrict__ out)
{
    const unsigned base = blockIdx.x * 512u + threadIdx.x;
    // two warp-strided units -> 4 front-batched loads (MLP=4)
    unit(base,        in, out);
    unit(base + 256u, in, out);
}

extern "C" void kernel_launch(void* const* d_in, const int* in_sizes, int n_in,
                              void* d_out, int out_size)
{
    const float* x = (const float*)d_in[0];
    float* y = (float*)d_out;

    maxpool2d_k2s2_kernel<<<TOTAL / 512, 256>>>(x, y);   // 25088 blocks, exact
}